// round 1
// baseline (speedup 1.0000x reference)
#include <cuda_runtime.h>
#include <math.h>

#define NN   166
#define NC   64
#define EMB  128
#define LOWD 64
#define FCIN 192
#define BEPS 1e-5f
#define MAXB 8192
#define MAXE 131072

// ---------------- device scratch (no allocations allowed) ----------------
__device__ int2  g_edges[MAXE];          // {src, bits(norm)} CSR by dst
__device__ int   g_rowptr[NN + 1];
__device__ float g_sum1[LOWD], g_sq1[LOWD];
__device__ float g_sum2[EMB],  g_sq2[EMB];
__device__ float g_Wlowf[LOWD * EMB], g_blowf[EMB];   // bn1 folded into linear_low
__device__ float g_Wfcf[FCIN * EMB],  g_bfcf[EMB];    // bn2 folded into fc1
__device__ float g_relu_low[MAXB * EMB];
__device__ float g_gfeat[MAXB * NC];

// ---------------- zero the batch-stat accumulators ----------------
__global__ void k_zero() {
    int t = threadIdx.x;
    if (t < LOWD) { g_sum1[t] = 0.f; g_sq1[t] = 0.f; }
    if (t < EMB)  { g_sum2[t] = 0.f; g_sq2[t] = 0.f; }
}

// ---------------- build CSR (dst-sorted) + sym-norm weights ----------------
// Handles both int64 and int32 edge_index storage (JAX x64 off => int32).
__global__ void k_graph(const void* __restrict__ ei_raw, int E) {
    __shared__ int   degs[NN];
    __shared__ float dinvs[NN];
    __shared__ int   curs[NN];
    __shared__ int   rps[NN + 1];
    __shared__ int   is64;

    const int t = threadIdx.x;
    const int* e32 = (const int*)ei_raw;

    if (t == 0) {
        int all0 = 1;
        int lim = 2 * E;  if (lim > 512) lim = 512;
        for (int i = 1; i < lim; i += 2) { if (e32[i] != 0) { all0 = 0; break; } }
        is64 = all0;
    }
    if (t < NN) degs[t] = 1;   // self loop
    __syncthreads();

    const long long* e64 = (const long long*)ei_raw;
    const int w64 = is64;

    for (int e = t; e < E; e += blockDim.x) {
        int d = w64 ? (int)e64[E + e] : e32[E + e];
        atomicAdd(&degs[d], 1);
    }
    __syncthreads();
    if (t == 0) {
        rps[0] = 0;
        for (int j = 0; j < NN; j++) rps[j + 1] = rps[j] + degs[j];
    }
    __syncthreads();
    if (t < NN) {
        dinvs[t] = rsqrtf((float)degs[t]);
        curs[t] = rps[t];
        g_rowptr[t] = rps[t];
    }
    if (t == 0) g_rowptr[NN] = rps[NN];
    __syncthreads();
    for (int e = t; e < E; e += blockDim.x) {
        int s = w64 ? (int)e64[e] : e32[e];
        int d = w64 ? (int)e64[E + e] : e32[E + e];
        int pos = atomicAdd(&curs[d], 1);
        g_edges[pos] = make_int2(s, __float_as_int(dinvs[s] * dinvs[d]));
    }
    if (t < NN) {
        int pos = atomicAdd(&curs[t], 1);
        g_edges[pos] = make_int2(t, __float_as_int(dinvs[t] * dinvs[t]));
    }
}

// ---------------- column stats of low_dim_features ----------------
__global__ void k_stats1(const float* __restrict__ low, int B) {
    const int t = threadIdx.x;
    const int c = t & 63, rg = t >> 6;       // 4 row groups x 64 cols
    float s = 0.f, q = 0.f;
    for (int r = blockIdx.x * 4 + rg; r < B; r += gridDim.x * 4) {
        float v = low[r * LOWD + c];
        s += v; q += v * v;
    }
    __shared__ float ss[256], qq[256];
    ss[t] = s; qq[t] = q;
    __syncthreads();
    if (rg == 0) {
        float S = ss[c] + ss[64 + c] + ss[128 + c] + ss[192 + c];
        float Q = qq[c] + qq[64 + c] + qq[128 + c] + qq[192 + c];
        atomicAdd(&g_sum1[c], S);
        atomicAdd(&g_sq1[c], Q);
    }
}

// ---------------- fold bn1 into linear_low ----------------
__global__ void k_fold1(const float* __restrict__ gbn, const float* __restrict__ bbn,
                        const float* __restrict__ Wlow, const float* __restrict__ bllow, int B) {
    __shared__ float s1[LOWD], t1[LOWD];
    const int t = threadIdx.x;
    if (t < LOWD) {
        float inv = 1.f / (float)B;
        float mu  = g_sum1[t] * inv;
        float var = g_sq1[t] * inv - mu * mu;
        float sc  = gbn[t] * rsqrtf(var + BEPS);
        s1[t] = sc;
        t1[t] = bbn[t] - mu * sc;
    }
    __syncthreads();
    for (int i = t; i < LOWD * EMB; i += blockDim.x)
        g_Wlowf[i] = s1[i >> 7] * Wlow[i];
    if (t < EMB) {
        float acc = bllow[t];
        for (int k = 0; k < LOWD; k++) acc += t1[k] * Wlow[k * EMB + t];
        g_blowf[t] = acc;
    }
}

// ---------------- relu(low @ W' + b') + column stats of the relu ----------------
__global__ void __launch_bounds__(128) k_lowmlp(const float* __restrict__ low, int B) {
    __shared__ float Wl[LOWD * EMB];
    __shared__ float bl[EMB];
    __shared__ float row[LOWD];
    const int t = threadIdx.x;   // 128 = output channel
    for (int i = t; i < LOWD * EMB; i += 128) Wl[i] = g_Wlowf[i];
    if (t < EMB) bl[t] = g_blowf[t];
    __syncthreads();

    const int rpb = (B + gridDim.x - 1) / gridDim.x;
    float ls = 0.f, lq = 0.f;
    for (int rr = 0; rr < rpb; rr++) {
        int r = blockIdx.x * rpb + rr;
        if (r < B && t < LOWD) row[t] = low[r * LOWD + t];
        __syncthreads();
        if (r < B) {
            float acc = bl[t];
            #pragma unroll
            for (int k = 0; k < LOWD; k++) acc += row[k] * Wl[k * EMB + t];
            acc = fmaxf(acc, 0.f);
            g_relu_low[(size_t)r * EMB + t] = acc;
            ls += acc; lq += acc * acc;
        }
        __syncthreads();
    }
    atomicAdd(&g_sum2[t], ls);
    atomicAdd(&g_sq2[t], lq);
}

// ---------------- fold bn2 into fc1 ----------------
__global__ void k_fold2(const float* __restrict__ glow, const float* __restrict__ blowbn,
                        const float* __restrict__ Wfc1, const float* __restrict__ bfc1, int B) {
    __shared__ float s2[EMB], t2[EMB];
    const int t = threadIdx.x;
    if (t < EMB) {
        float inv = 1.f / (float)B;
        float mu  = g_sum2[t] * inv;
        float var = g_sq2[t] * inv - mu * mu;
        float sc  = glow[t] * rsqrtf(var + BEPS);
        s2[t] = sc;
        t2[t] = blowbn[t] - mu * sc;
    }
    __syncthreads();
    for (int i = t; i < NC * EMB; i += blockDim.x) g_Wfcf[i] = Wfc1[i];             // g rows
    for (int i = t; i < EMB * EMB; i += blockDim.x) {                                // low rows, bn folded
        int k = i >> 7;
        g_Wfcf[NC * EMB + i] = s2[k] * Wfc1[NC * EMB + i];
    }
    if (t < EMB) {
        float acc = bfc1[t];
        for (int k = 0; k < EMB; k++) acc += t2[k] * Wfc1[(NC + k) * EMB + t];
        g_bfcf[t] = acc;
    }
}

// ---------------- fused GCN: per-sample conv1 -> conv2 -> mean pool ----------------
__device__ __forceinline__ void fma16(float acc[4], float4 y,
                                      float4 w0, float4 w1, float4 w2, float4 w3) {
    acc[0] += y.x * w0.x; acc[1] += y.x * w0.y; acc[2] += y.x * w0.z; acc[3] += y.x * w0.w;
    acc[0] += y.y * w1.x; acc[1] += y.y * w1.y; acc[2] += y.y * w1.z; acc[3] += y.y * w1.w;
    acc[0] += y.z * w2.x; acc[1] += y.z * w2.y; acc[2] += y.z * w2.z; acc[3] += y.z * w2.w;
    acc[0] += y.w * w3.x; acc[1] += y.w * w3.y; acc[2] += y.w * w3.z; acc[3] += y.w * w3.w;
}

__global__ void __launch_bounds__(512) k_gcn(const float* __restrict__ high,
                                             const float* __restrict__ W1, const float* __restrict__ b1,
                                             const float* __restrict__ W2, const float* __restrict__ b2,
                                             int EC) {
    extern __shared__ float sm[];
    float* h1   = sm;                  // NN*64
    float* yvb  = h1 + NN * NC;        // NN*64
    float* W2s  = yvb + NN * NC;       // 4096
    float* xs   = W2s + 4096;          // 498
    float* y0s  = xs + NN * 3;         // 498
    float* W1s  = y0s + NN * 3;        // 192
    float* b1s  = W1s + 192;           // 64
    float* b2s  = b1s + 64;            // 64
    float* gsum = b2s + 64;            // 64
    int2*  se   = (int2*)(gsum + 64);  // EC entries
    int*   srp  = (int*)(se + EC);     // NN+1

    const int t = threadIdx.x;
    const int b = blockIdx.x;

    const float* xrow = high + (size_t)b * (NN * 3);
    for (int i = t; i < NN * 3; i += 512) xs[i] = xrow[i];
    for (int i = t; i < NC * NC; i += 512) W2s[i] = W2[i];
    for (int i = t; i < EC; i += 512) se[i] = g_edges[i];
    if (t < NN + 1) srp[t] = g_rowptr[t];
    if (t < 192) W1s[t] = W1[t];
    if (t < 64) { b1s[t] = b1[t]; b2s[t] = b2[t]; gsum[t] = 0.f; }
    __syncthreads();

    // y0 = A x  (3 channels)
    if (t < NN) {
        int e0 = srp[t], e1 = srp[t + 1];
        float a0 = 0.f, a1 = 0.f, a2 = 0.f;
        for (int e = e0; e < e1; e++) {
            int2 ed = se[e];
            float w = __int_as_float(ed.y);
            int s3 = ed.x * 3;
            a0 += w * xs[s3]; a1 += w * xs[s3 + 1]; a2 += w * xs[s3 + 2];
        }
        y0s[t * 3] = a0; y0s[t * 3 + 1] = a1; y0s[t * 3 + 2] = a2;
    }
    __syncthreads();

    // h1 = relu(y0 @ W1 + b1)
    for (int i = t; i < NN * NC; i += 512) {
        int j = i >> 6, c = i & 63;
        float v = b1s[c] + y0s[j * 3] * W1s[c] + y0s[j * 3 + 1] * W1s[NC + c]
                         + y0s[j * 3 + 2] * W1s[2 * NC + c];
        h1[i] = fmaxf(v, 0.f);
    }
    __syncthreads();

    // yv = A h1   (warp shares one row j -> uniform edge reads, contiguous h1 reads)
    for (int i = t; i < NN * NC; i += 512) {
        int j = i >> 6, c = i & 63;
        int e0 = srp[j], e1 = srp[j + 1];
        float acc = 0.f;
        int e = e0;
        for (; e + 2 <= e1; e += 2) {
            int2 ea = se[e], eb = se[e + 1];
            acc += __int_as_float(ea.y) * h1[(ea.x << 6) + c];
            acc += __int_as_float(eb.y) * h1[(eb.x << 6) + c];
        }
        if (e < e1) {
            int2 ea = se[e];
            acc += __int_as_float(ea.y) * h1[(ea.x << 6) + c];
        }
        yvb[i] = acc;
    }
    __syncthreads();

    // h2 = relu(yv @ W2 + b2); g = column mean.  4j x 4c register blocking.
    {
        const int ct = t & 15;       // 4 channels: 4*ct .. 4*ct+3
        const int jt = t >> 4;       // 0..31
        const float4* W24 = (const float4*)W2s;
        const float4* yv4 = (const float4*)yvb;
        float gp[4] = {0.f, 0.f, 0.f, 0.f};

        #pragma unroll
        for (int pass = 0; pass < 2; pass++) {
            int jb = pass * 128 + jt * 4;
            if (jb < NN) {
                float acc0[4] = {0,0,0,0}, acc1[4] = {0,0,0,0};
                float acc2[4] = {0,0,0,0}, acc3[4] = {0,0,0,0};
                int r0 = jb * 16;
                int r1 = min(jb + 1, NN - 1) * 16;
                int r2 = min(jb + 2, NN - 1) * 16;
                int r3 = min(jb + 3, NN - 1) * 16;
                #pragma unroll 4
                for (int k4 = 0; k4 < 16; k4++) {
                    float4 ya = yv4[r0 + k4];
                    float4 yb = yv4[r1 + k4];
                    float4 yc = yv4[r2 + k4];
                    float4 yd = yv4[r3 + k4];
                    float4 w0 = W24[(k4 * 4 + 0) * 16 + ct];
                    float4 w1 = W24[(k4 * 4 + 1) * 16 + ct];
                    float4 w2 = W24[(k4 * 4 + 2) * 16 + ct];
                    float4 w3 = W24[(k4 * 4 + 3) * 16 + ct];
                    fma16(acc0, ya, w0, w1, w2, w3);
                    fma16(acc1, yb, w0, w1, w2, w3);
                    fma16(acc2, yc, w0, w1, w2, w3);
                    fma16(acc3, yd, w0, w1, w2, w3);
                }
                float bb0 = b2s[ct * 4 + 0], bb1 = b2s[ct * 4 + 1];
                float bb2 = b2s[ct * 4 + 2], bb3 = b2s[ct * 4 + 3];
                if (jb + 0 < NN) {
                    gp[0] += fmaxf(acc0[0] + bb0, 0.f); gp[1] += fmaxf(acc0[1] + bb1, 0.f);
                    gp[2] += fmaxf(acc0[2] + bb2, 0.f); gp[3] += fmaxf(acc0[3] + bb3, 0.f);
                }
                if (jb + 1 < NN) {
                    gp[0] += fmaxf(acc1[0] + bb0, 0.f); gp[1] += fmaxf(acc1[1] + bb1, 0.f);
                    gp[2] += fmaxf(acc1[2] + bb2, 0.f); gp[3] += fmaxf(acc1[3] + bb3, 0.f);
                }
                if (jb + 2 < NN) {
                    gp[0] += fmaxf(acc2[0] + bb0, 0.f); gp[1] += fmaxf(acc2[1] + bb1, 0.f);
                    gp[2] += fmaxf(acc2[2] + bb2, 0.f); gp[3] += fmaxf(acc2[3] + bb3, 0.f);
                }
                if (jb + 3 < NN) {
                    gp[0] += fmaxf(acc3[0] + bb0, 0.f); gp[1] += fmaxf(acc3[1] + bb1, 0.f);
                    gp[2] += fmaxf(acc3[2] + bb2, 0.f); gp[3] += fmaxf(acc3[3] + bb3, 0.f);
                }
            }
        }
        atomicAdd(&gsum[ct * 4 + 0], gp[0]);
        atomicAdd(&gsum[ct * 4 + 1], gp[1]);
        atomicAdd(&gsum[ct * 4 + 2], gp[2]);
        atomicAdd(&gsum[ct * 4 + 3], gp[3]);
    }
    __syncthreads();
    if (t < NC) g_gfeat[(size_t)b * NC + t] = gsum[t] * (1.f / (float)NN);
}

// ---------------- head: fc1(folded bn2) + relu + classifier + log_softmax ----------------
__global__ void __launch_bounds__(256) k_head(const float* __restrict__ Wcls,
                                              const float* __restrict__ bcls,
                                              float* __restrict__ out, int B) {
    const int t = threadIdx.x;
    const int c = t & 127;
    const int kh = t >> 7;     // 0 or 1: halves of the 192-dim input

    __shared__ float comb[FCIN];
    __shared__ float partial[2 * EMB];
    __shared__ float bfcs[EMB];
    __shared__ float wcl0[EMB], wcl1[EMB];
    __shared__ float red[8];

    if (t < EMB) {
        bfcs[t] = g_bfcf[t];
        wcl0[t] = Wcls[t * 2];
        wcl1[t] = Wcls[t * 2 + 1];
    }
    float w[96];
    #pragma unroll
    for (int i = 0; i < 96; i++) w[i] = g_Wfcf[(kh * 96 + i) * EMB + c];

    const int spb = (B + gridDim.x - 1) / gridDim.x;
    __syncthreads();

    for (int it = 0; it < spb; it++) {
        int s = blockIdx.x * spb + it;
        bool valid = (s < B);
        if (valid) {
            if (t < NC) comb[t] = g_gfeat[(size_t)s * NC + t];
            int u = t - NC;
            if (u >= 0 && u < EMB) comb[NC + u] = g_relu_low[(size_t)s * EMB + u];
        }
        __syncthreads();
        if (valid) {
            const float* cb = comb + kh * 96;
            float a0 = 0.f, a1 = 0.f, a2 = 0.f, a3 = 0.f;
            #pragma unroll
            for (int i = 0; i < 96; i += 4) {
                a0 += w[i] * cb[i];
                a1 += w[i + 1] * cb[i + 1];
                a2 += w[i + 2] * cb[i + 2];
                a3 += w[i + 3] * cb[i + 3];
            }
            partial[kh * EMB + c] = (a0 + a1) + (a2 + a3);
        }
        __syncthreads();
        if (valid && kh == 0) {
            float h = fmaxf(partial[c] + partial[EMB + c] + bfcs[c], 0.f);
            float p0 = h * wcl0[c];
            float p1 = h * wcl1[c];
            #pragma unroll
            for (int o = 16; o > 0; o >>= 1) {
                p0 += __shfl_down_sync(0xffffffffu, p0, o);
                p1 += __shfl_down_sync(0xffffffffu, p1, o);
            }
            if ((c & 31) == 0) { red[c >> 5] = p0; red[4 + (c >> 5)] = p1; }
        }
        __syncthreads();
        if (valid && t == 0) {
            float l0 = red[0] + red[1] + red[2] + red[3] + bcls[0];
            float l1 = red[4] + red[5] + red[6] + red[7] + bcls[1];
            float m = fmaxf(l0, l1);
            float lse = m + logf(expf(l0 - m) + expf(l1 - m));
            out[(size_t)s * 2 + 0] = l0 - lse;
            out[(size_t)s * 2 + 1] = l1 - lse;
        }
        __syncthreads();
    }
}

// ---------------- launch ----------------
extern "C" void kernel_launch(void* const* d_in, const int* in_sizes, int n_in,
                              void* d_out, int out_size) {
    const float* high  = (const float*)d_in[0];
    const float* low   = (const float*)d_in[1];
    const void*  ei    = d_in[2];
    const float* g_bn  = (const float*)d_in[3];
    const float* b_bn  = (const float*)d_in[4];
    const float* W_low = (const float*)d_in[5];
    const float* bl_lw = (const float*)d_in[6];
    const float* g_lo  = (const float*)d_in[7];
    const float* b_lo  = (const float*)d_in[8];
    const float* W1    = (const float*)d_in[9];
    const float* b1    = (const float*)d_in[10];
    const float* W2    = (const float*)d_in[11];
    const float* b2    = (const float*)d_in[12];
    const float* Wfc1  = (const float*)d_in[13];
    const float* bfc1  = (const float*)d_in[14];
    const float* Wcls  = (const float*)d_in[15];
    const float* bcls  = (const float*)d_in[16];

    int B = in_sizes[0] / (NN * 3);
    int E = in_sizes[2] / 2;
    int EC = E + NN;
    float* out = (float*)d_out;

    k_zero<<<1, 256>>>();
    k_graph<<<1, 256>>>(ei, E);
    k_stats1<<<64, 256>>>(low, B);
    k_fold1<<<1, 256>>>(g_bn, b_bn, W_low, bl_lw, B);
    k_lowmlp<<<128, 128>>>(low, B);
    k_fold2<<<1, 256>>>(g_lo, b_lo, Wfc1, bfc1, B);

    int smbytes = (NN * NC * 2 + 4096 + NN * 3 * 2 + 192 + 64 + 64 + 64) * 4
                + EC * 8 + (NN + 1) * 4;
    cudaFuncSetAttribute(k_gcn, cudaFuncAttributeMaxDynamicSharedMemorySize, smbytes);
    k_gcn<<<B, 512, smbytes>>>(high, W1, b1, W2, b2, EC);

    k_head<<<128, 256>>>(Wcls, bcls, out, B);
}

// round 2
// speedup vs baseline: 1.1889x; 1.1889x over previous
#include <cuda_runtime.h>
#include <math.h>

#define NN   166
#define NC   64
#define EMB  128
#define LOWD 64
#define FCIN 192
#define BEPS 1e-5f
#define MAXB 8192
#define MAXE 131072

// ---------------- device scratch ----------------
__device__ unsigned g_edgesP[MAXE];      // (fp32 weight top 24 bits) | src(8 bits), CSR by dst
__device__ int   g_rowptr[NN + 1];
__device__ float g_sum1[LOWD], g_sq1[LOWD];
__device__ float g_sum2[EMB],  g_sq2[EMB];
__device__ float g_Wfcf[FCIN * EMB],  g_bfcf[EMB];    // bn2 folded into fc1
__device__ float g_relu_low[MAXB * EMB];
__device__ float g_gfeat[MAXB * NC];

// ---------------- CSR build (dst-sorted) + sym-norm, packed; also zero stats ----------------
__global__ void k_graph(const void* __restrict__ ei_raw, int E) {
    __shared__ int   degs[NN];
    __shared__ float dinvs[NN];
    __shared__ int   curs[NN];
    __shared__ int   rps[NN + 1];
    __shared__ int   is64;

    const int t = threadIdx.x;
    const int* e32 = (const int*)ei_raw;

    if (t < LOWD) { g_sum1[t] = 0.f; g_sq1[t] = 0.f; }
    if (t < EMB)  { g_sum2[t] = 0.f; g_sq2[t] = 0.f; }

    if (t == 0) {
        int all0 = 1;
        int lim = 2 * E;  if (lim > 512) lim = 512;
        for (int i = 1; i < lim; i += 2) { if (e32[i] != 0) { all0 = 0; break; } }
        is64 = all0;
    }
    if (t < NN) degs[t] = 1;   // self loop
    __syncthreads();

    const long long* e64 = (const long long*)ei_raw;
    const int w64 = is64;

    for (int e = t; e < E; e += blockDim.x) {
        int d = w64 ? (int)e64[E + e] : e32[E + e];
        atomicAdd(&degs[d], 1);
    }
    __syncthreads();
    if (t == 0) {
        rps[0] = 0;
        for (int j = 0; j < NN; j++) rps[j + 1] = rps[j] + degs[j];
    }
    __syncthreads();
    if (t < NN) {
        dinvs[t] = rsqrtf((float)degs[t]);
        curs[t] = rps[t];
        g_rowptr[t] = rps[t];
    }
    if (t == 0) g_rowptr[NN] = rps[NN];
    __syncthreads();
    for (int e = t; e < E; e += blockDim.x) {
        int s = w64 ? (int)e64[e] : e32[e];
        int d = w64 ? (int)e64[E + e] : e32[E + e];
        int pos = atomicAdd(&curs[d], 1);
        unsigned wb = __float_as_uint(dinvs[s] * dinvs[d]);
        g_edgesP[pos] = (wb & 0xFFFFFF00u) | (unsigned)s;
    }
    if (t < NN) {
        int pos = atomicAdd(&curs[t], 1);
        unsigned wb = __float_as_uint(dinvs[t] * dinvs[t]);
        g_edgesP[pos] = (wb & 0xFFFFFF00u) | (unsigned)t;
    }
}

// ---------------- column stats of low_dim_features ----------------
__global__ void k_stats1(const float* __restrict__ low, int B) {
    const int t = threadIdx.x;
    const int c = t & 63, rg = t >> 6;
    float s = 0.f, q = 0.f;
    for (int r = blockIdx.x * 4 + rg; r < B; r += gridDim.x * 4) {
        float v = low[r * LOWD + c];
        s += v; q += v * v;
    }
    __shared__ float ss[256], qq[256];
    ss[t] = s; qq[t] = q;
    __syncthreads();
    if (rg == 0) {
        float S = ss[c] + ss[64 + c] + ss[128 + c] + ss[192 + c];
        float Q = qq[c] + qq[64 + c] + qq[128 + c] + qq[192 + c];
        atomicAdd(&g_sum1[c], S);
        atomicAdd(&g_sq1[c], Q);
    }
}

// ---------------- fold bn1 + linear + relu + bn2-stats (W in registers) ----------------
__global__ void __launch_bounds__(128) k_lowmlp(const float* __restrict__ low,
                                                const float* __restrict__ gbn, const float* __restrict__ bbn,
                                                const float* __restrict__ Wlow, const float* __restrict__ bllow,
                                                int B) {
    __shared__ float s1[LOWD], t1[LOWD];
    __shared__ float rows[8 * LOWD];
    const int t = threadIdx.x;   // output channel 0..127

    if (t < LOWD) {
        float inv = 1.f / (float)B;
        float mu  = g_sum1[t] * inv;
        float var = g_sq1[t] * inv - mu * mu;
        float sc  = gbn[t] * rsqrtf(var + BEPS);
        s1[t] = sc;
        t1[t] = bbn[t] - mu * sc;
    }
    __syncthreads();

    float w[LOWD];
    float bias = bllow[t];
    #pragma unroll
    for (int k = 0; k < LOWD; k++) {
        float v = Wlow[k * EMB + t];
        w[k] = s1[k] * v;
        bias += t1[k] * v;
    }

    const int spb = (B + gridDim.x - 1) / gridDim.x;
    float ls = 0.f, lq = 0.f;
    const int r8 = t >> 4, q16 = t & 15;

    for (int it = 0; it < spb; it += 8) {
        int base = blockIdx.x * spb + it;
        int rrow = base + r8;
        if (rrow < B)
            ((float4*)rows)[t] = ((const float4*)low)[rrow * 16 + q16];
        __syncthreads();
        #pragma unroll
        for (int s = 0; s < 8; s++) {
            int r = base + s;
            if (r < B) {
                float acc = bias;
                const float4* rp = (const float4*)(rows + s * LOWD);
                #pragma unroll
                for (int k4 = 0; k4 < 16; k4++) {
                    float4 rv = rp[k4];
                    acc += rv.x * w[k4 * 4 + 0];
                    acc += rv.y * w[k4 * 4 + 1];
                    acc += rv.z * w[k4 * 4 + 2];
                    acc += rv.w * w[k4 * 4 + 3];
                }
                acc = fmaxf(acc, 0.f);
                g_relu_low[(size_t)r * EMB + t] = acc;
                ls += acc; lq += acc * acc;
            }
        }
        __syncthreads();
    }
    atomicAdd(&g_sum2[t], ls);
    atomicAdd(&g_sq2[t], lq);
}

// ---------------- fold bn2 into fc1 ----------------
__global__ void k_fold2(const float* __restrict__ glow, const float* __restrict__ blowbn,
                        const float* __restrict__ Wfc1, const float* __restrict__ bfc1, int B) {
    __shared__ float s2[EMB], t2[EMB];
    const int t = threadIdx.x;
    if (t < EMB) {
        float inv = 1.f / (float)B;
        float mu  = g_sum2[t] * inv;
        float var = g_sq2[t] * inv - mu * mu;
        float sc  = glow[t] * rsqrtf(var + BEPS);
        s2[t] = sc;
        t2[t] = blowbn[t] - mu * sc;
    }
    __syncthreads();
    for (int i = t; i < NC * EMB; i += blockDim.x) g_Wfcf[i] = Wfc1[i];
    for (int i = t; i < EMB * EMB; i += blockDim.x) {
        int k = i >> 7;
        g_Wfcf[NC * EMB + i] = s2[k] * Wfc1[NC * EMB + i];
    }
    if (t < EMB) {
        float acc = bfc1[t];
        for (int k = 0; k < EMB; k++) acc += t2[k] * Wfc1[(NC + k) * EMB + t];
        g_bfcf[t] = acc;
    }
}

// ---------------- persistent fused GCN ----------------
__global__ void __launch_bounds__(512, 2) k_gcn(const float* __restrict__ high,
                                                const float* __restrict__ W1, const float* __restrict__ b1,
                                                const float* __restrict__ W2, const float* __restrict__ b2,
                                                int EC, int B) {
    extern __shared__ float sm[];
    float*    h1  = sm;                       // 10624
    float*    yv  = h1 + NN * NC;             // 4096  (64-row tile; reused as reduce buf)
    float*    W2s = yv + 4096;                // 4096
    float*    xs  = W2s + 4096;               // 498
    float*    y0s = xs + 498;                 // 498
    float*    W1s = y0s + 498;                // 192
    float*    b1s = W1s + 192;                // 64
    float*    b2s = b1s + 64;                 // 64
    int*      srp = (int*)(b2s + 64);         // 168
    unsigned* se  = (unsigned*)(srp + 168);   // EC

    const int t = threadIdx.x;

    for (int i = t; i < NC * NC; i += 512) W2s[i] = W2[i];
    for (int i = t; i < EC; i += 512) se[i] = g_edgesP[i];
    if (t < NN + 1) srp[t] = g_rowptr[t];
    if (t < 192) W1s[t] = W1[t];
    if (t < 64) { b1s[t] = b1[t]; b2s[t] = b2[t]; }
    __syncthreads();

    const int lane = t & 31, wrp = t >> 5;    // aggregation mapping (warp = row)
    const int ct = t & 15, jt = t >> 4;       // matmul mapping

    for (int b = blockIdx.x; b < B; b += gridDim.x) {
        // ---- load x ----
        const float2* xrow = (const float2*)(high + (size_t)b * (NN * 3));
        if (t < 249) ((float2*)xs)[t] = xrow[t];
        __syncthreads();

        // ---- y0 = A x (3 channels) ----
        if (t < NN * 3) {
            int j = t / 3, c = t - j * 3;
            int e0 = srp[j], e1 = srp[j + 1];
            float a = 0.f;
            for (int e = e0; e < e1; e++) {
                unsigned u = se[e];
                a += __uint_as_float(u & 0xFFFFFF00u) * xs[(u & 0xFFu) * 3 + c];
            }
            y0s[t] = a;
        }
        __syncthreads();

        // ---- h1 = relu(y0 W1 + b1) ----
        for (int i = t; i < NN * NC; i += 512) {
            int j = i >> 6, c = i & 63;
            float v = b1s[c] + y0s[j * 3] * W1s[c] + y0s[j * 3 + 1] * W1s[NC + c]
                             + y0s[j * 3 + 2] * W1s[2 * NC + c];
            h1[i] = fmaxf(v, 0.f);
        }
        __syncthreads();

        // ---- conv2: 3 tiles of 64 rows; agg -> matmul+pool ----
        float gp0 = 0.f, gp1 = 0.f, gp2 = 0.f, gp3 = 0.f;

        #pragma unroll
        for (int tile = 0; tile < 3; tile++) {
            const int jbase = tile * 64;

            // aggregation: yv[jl] = (A h1)[jbase+jl]; warp per row, lane = 2 channels
            #pragma unroll
            for (int rr = 0; rr < 4; rr++) {
                int j = jbase + wrp + rr * 16;
                if (j < NN) {
                    int e0 = srp[j], e1 = srp[j + 1];
                    float ax = 0.f, ay = 0.f;
                    int e = e0;
                    for (; e + 2 <= e1; e += 2) {
                        unsigned ua = se[e], ub = se[e + 1];
                        float wa = __uint_as_float(ua & 0xFFFFFF00u);
                        float wb = __uint_as_float(ub & 0xFFFFFF00u);
                        float2 ha = *(const float2*)(h1 + ((ua & 0xFFu) << 6) + 2 * lane);
                        float2 hb = *(const float2*)(h1 + ((ub & 0xFFu) << 6) + 2 * lane);
                        ax += wa * ha.x; ay += wa * ha.y;
                        ax += wb * hb.x; ay += wb * hb.y;
                    }
                    if (e < e1) {
                        unsigned ua = se[e];
                        float wa = __uint_as_float(ua & 0xFFFFFF00u);
                        float2 ha = *(const float2*)(h1 + ((ua & 0xFFu) << 6) + 2 * lane);
                        ax += wa * ha.x; ay += wa * ha.y;
                    }
                    *(float2*)(yv + (j - jbase) * NC + 2 * lane) = make_float2(ax, ay);
                }
            }
            __syncthreads();

            // matmul: rows jt*2, jt*2+1 (local), channels 4ct..4ct+3
            {
                const int r0 = jt * 2, r1 = jt * 2 + 1;
                const bool v0 = (jbase + r0) < NN, v1 = (jbase + r1) < NN;
                const float4* yv4 = (const float4*)yv;
                const float4* W24 = (const float4*)W2s;
                float a00 = 0.f, a01 = 0.f, a02 = 0.f, a03 = 0.f;
                float a10 = 0.f, a11 = 0.f, a12 = 0.f, a13 = 0.f;
                #pragma unroll
                for (int k4 = 0; k4 < 16; k4++) {
                    float4 ya = yv4[r0 * 16 + k4];
                    float4 yb = yv4[r1 * 16 + k4];
                    float4 w0 = W24[(k4 * 4 + 0) * 16 + ct];
                    float4 w1 = W24[(k4 * 4 + 1) * 16 + ct];
                    float4 w2 = W24[(k4 * 4 + 2) * 16 + ct];
                    float4 w3 = W24[(k4 * 4 + 3) * 16 + ct];
                    a00 += ya.x * w0.x; a01 += ya.x * w0.y; a02 += ya.x * w0.z; a03 += ya.x * w0.w;
                    a00 += ya.y * w1.x; a01 += ya.y * w1.y; a02 += ya.y * w1.z; a03 += ya.y * w1.w;
                    a00 += ya.z * w2.x; a01 += ya.z * w2.y; a02 += ya.z * w2.z; a03 += ya.z * w2.w;
                    a00 += ya.w * w3.x; a01 += ya.w * w3.y; a02 += ya.w * w3.z; a03 += ya.w * w3.w;
                    a10 += yb.x * w0.x; a11 += yb.x * w0.y; a12 += yb.x * w0.z; a13 += yb.x * w0.w;
                    a10 += yb.y * w1.x; a11 += yb.y * w1.y; a12 += yb.y * w1.z; a13 += yb.y * w1.w;
                    a10 += yb.z * w2.x; a11 += yb.z * w2.y; a12 += yb.z * w2.z; a13 += yb.z * w2.w;
                    a10 += yb.w * w3.x; a11 += yb.w * w3.y; a12 += yb.w * w3.z; a13 += yb.w * w3.w;
                }
                float bb0 = b2s[4 * ct + 0], bb1 = b2s[4 * ct + 1];
                float bb2 = b2s[4 * ct + 2], bb3 = b2s[4 * ct + 3];
                if (v0) {
                    gp0 += fmaxf(a00 + bb0, 0.f); gp1 += fmaxf(a01 + bb1, 0.f);
                    gp2 += fmaxf(a02 + bb2, 0.f); gp3 += fmaxf(a03 + bb3, 0.f);
                }
                if (v1) {
                    gp0 += fmaxf(a10 + bb0, 0.f); gp1 += fmaxf(a11 + bb1, 0.f);
                    gp2 += fmaxf(a12 + bb2, 0.f); gp3 += fmaxf(a13 + bb3, 0.f);
                }
            }
            __syncthreads();
        }

        // ---- reduce 32 jt-partials per channel (reuse yv) ----
        yv[jt * 64 + 4 * ct + 0] = gp0;
        yv[jt * 64 + 4 * ct + 1] = gp1;
        yv[jt * 64 + 4 * ct + 2] = gp2;
        yv[jt * 64 + 4 * ct + 3] = gp3;
        __syncthreads();
        if (t < NC) {
            float a = 0.f;
            #pragma unroll
            for (int g = 0; g < 32; g++) a += yv[g * 64 + t];
            g_gfeat[(size_t)b * NC + t] = a * (1.f / (float)NN);
        }
        __syncthreads();
    }
}

// ---------------- head: fc1(folded bn2) + relu + classifier + log_softmax ----------------
__global__ void __launch_bounds__(256) k_head(const float* __restrict__ Wcls,
                                              const float* __restrict__ bcls,
                                              float* __restrict__ out, int B) {
    const int t = threadIdx.x;
    const int c = t & 127;
    const int kh = t >> 7;

    __shared__ float comb[FCIN];
    __shared__ float partial[2 * EMB];
    __shared__ float bfcs[EMB];
    __shared__ float wcl0[EMB], wcl1[EMB];
    __shared__ float red[8];

    if (t < EMB) {
        bfcs[t] = g_bfcf[t];
        wcl0[t] = Wcls[t * 2];
        wcl1[t] = Wcls[t * 2 + 1];
    }
    float w[96];
    #pragma unroll
    for (int i = 0; i < 96; i++) w[i] = g_Wfcf[(kh * 96 + i) * EMB + c];

    const int spb = (B + gridDim.x - 1) / gridDim.x;
    __syncthreads();

    for (int it = 0; it < spb; it++) {
        int s = blockIdx.x * spb + it;
        bool valid = (s < B);
        if (valid) {
            if (t < NC) comb[t] = g_gfeat[(size_t)s * NC + t];
            int u = t - NC;
            if (u >= 0 && u < EMB) comb[NC + u] = g_relu_low[(size_t)s * EMB + u];
        }
        __syncthreads();
        if (valid) {
            const float* cb = comb + kh * 96;
            float a0 = 0.f, a1 = 0.f, a2 = 0.f, a3 = 0.f;
            #pragma unroll
            for (int i = 0; i < 96; i += 4) {
                a0 += w[i] * cb[i];
                a1 += w[i + 1] * cb[i + 1];
                a2 += w[i + 2] * cb[i + 2];
                a3 += w[i + 3] * cb[i + 3];
            }
            partial[kh * EMB + c] = (a0 + a1) + (a2 + a3);
        }
        __syncthreads();
        if (valid && kh == 0) {
            float h = fmaxf(partial[c] + partial[EMB + c] + bfcs[c], 0.f);
            float p0 = h * wcl0[c];
            float p1 = h * wcl1[c];
            #pragma unroll
            for (int o = 16; o > 0; o >>= 1) {
                p0 += __shfl_down_sync(0xffffffffu, p0, o);
                p1 += __shfl_down_sync(0xffffffffu, p1, o);
            }
            if ((c & 31) == 0) { red[c >> 5] = p0; red[4 + (c >> 5)] = p1; }
        }
        __syncthreads();
        if (valid && t == 0) {
            float l0 = red[0] + red[1] + red[2] + red[3] + bcls[0];
            float l1 = red[4] + red[5] + red[6] + red[7] + bcls[1];
            float m = fmaxf(l0, l1);
            float lse = m + logf(expf(l0 - m) + expf(l1 - m));
            out[(size_t)s * 2 + 0] = l0 - lse;
            out[(size_t)s * 2 + 1] = l1 - lse;
        }
        __syncthreads();
    }
}

// ---------------- launch ----------------
extern "C" void kernel_launch(void* const* d_in, const int* in_sizes, int n_in,
                              void* d_out, int out_size) {
    const float* high  = (const float*)d_in[0];
    const float* low   = (const float*)d_in[1];
    const void*  ei    = d_in[2];
    const float* g_bn  = (const float*)d_in[3];
    const float* b_bn  = (const float*)d_in[4];
    const float* W_low = (const float*)d_in[5];
    const float* bl_lw = (const float*)d_in[6];
    const float* g_lo  = (const float*)d_in[7];
    const float* b_lo  = (const float*)d_in[8];
    const float* W1    = (const float*)d_in[9];
    const float* b1    = (const float*)d_in[10];
    const float* W2    = (const float*)d_in[11];
    const float* b2    = (const float*)d_in[12];
    const float* Wfc1  = (const float*)d_in[13];
    const float* bfc1  = (const float*)d_in[14];
    const float* Wcls  = (const float*)d_in[15];
    const float* bcls  = (const float*)d_in[16];

    int B = in_sizes[0] / (NN * 3);
    int E = in_sizes[2] / 2;
    int EC = E + NN;
    float* out = (float*)d_out;

    k_graph<<<1, 256>>>(ei, E);
    k_stats1<<<64, 256>>>(low, B);
    k_lowmlp<<<128, 128>>>(low, g_bn, b_bn, W_low, bl_lw, B);

    int smbytes = (NN * NC + 4096 + 4096 + 498 + 498 + 192 + 64 + 64) * 4
                + 168 * 4 + EC * 4;
    cudaFuncSetAttribute(k_gcn, cudaFuncAttributeMaxDynamicSharedMemorySize, smbytes);
    int grid = 2 * 148;
    if (grid > B) grid = B;
    k_gcn<<<grid, 512, smbytes>>>(high, W1, b1, W2, b2, EC, B);

    k_fold2<<<1, 256>>>(g_lo, b_lo, Wfc1, bfc1, B);
    k_head<<<128, 256>>>(Wcls, bcls, out, B);
}

// round 5
// speedup vs baseline: 2.6536x; 2.2321x over previous
#include <cuda_runtime.h>
#include <cuda_fp16.h>
#include <math.h>
#include <stdint.h>

#define NN   166
#define NC   64
#define EMB  128
#define LOWD 64
#define FCIN 192
#define BEPS 1e-5f
#define MAXB 8192
#define MAXE 131072

// ---- k_gcn smem layout (bytes; every image offset 1024-aligned) ----
#define OFF_AD   0        // A_dense fp16 [176 x 192] swz      67584
#define OFF_H1   67584    // h1 fp16 [176 x 64] swz            22528
#define OFF_WT   90112    // W2^T fp16 [64 x 64] swz            8192
#define OFF_ZT   98304    // z^T fp16 [64 x 192] swz           24576
#define OFF_E    122880   // packed edges (cap 4352)           17408
#define OFF_XS   140288   // x fp32 (498, padded)               2048
#define OFF_Y0   142336   // y0 fp32 (498, padded)              2048
#define OFF_RP   144384   // rowptr (168)                        672
#define OFF_B1   145056   // b1 fp32 (64)
#define OFF_B2   145312   // b2 fp32 (64)
#define OFF_W1   145568   // W1 fp32 (192)
#define OFF_POOL 146336   // pool fp32 (64)
#define GCN_SMEM 146592

// ---------------- device scratch ----------------
__device__ unsigned g_edgesP[MAXE];
__device__ int   g_rowptr[NN + 1];
__device__ float g_Adense[256 * 192];
__device__ float g_sum1[LOWD], g_sq1[LOWD];
__device__ float g_sum2[EMB],  g_sq2[EMB];
__device__ float g_Wfcf[FCIN * EMB],  g_bfcf[EMB];
__device__ float g_relu_low[MAXB * EMB];
__device__ float g_gfeat[MAXB * NC];

// ---------------- helpers ----------------
__device__ __forceinline__ uint32_t swz(uint32_t o) { return o ^ ((o >> 3) & 0x70); }

__device__ __forceinline__ void mma8(float* d, uint32_t a0, uint32_t a1, uint32_t a2, uint32_t a3,
                                     uint32_t b0, uint32_t b1) {
    asm volatile(
        "mma.sync.aligned.m16n8k16.row.col.f32.f16.f16.f32 "
        "{%0,%1,%2,%3}, {%4,%5,%6,%7}, {%8,%9}, {%0,%1,%2,%3};"
        : "+f"(d[0]), "+f"(d[1]), "+f"(d[2]), "+f"(d[3])
        : "r"(a0), "r"(a1), "r"(a2), "r"(a3), "r"(b0), "r"(b1));
}

// ---------------- CSR + dense A build; zero stats ----------------
__global__ void k_graph(const void* __restrict__ ei_raw, int E) {
    __shared__ int   degs[NN];
    __shared__ float dinvs[NN];
    __shared__ int   curs[NN];
    __shared__ int   rps[NN + 1];
    __shared__ int   is64;

    const int t = threadIdx.x;
    const int* e32 = (const int*)ei_raw;

    for (int i = t; i < 256 * 192; i += 256) g_Adense[i] = 0.f;
    if (t < LOWD) { g_sum1[t] = 0.f; g_sq1[t] = 0.f; }
    if (t < EMB)  { g_sum2[t] = 0.f; g_sq2[t] = 0.f; }

    if (t == 0) {
        int all0 = 1;
        int lim = 2 * E; if (lim > 512) lim = 512;
        for (int i = 1; i < lim; i += 2) if (e32[i] != 0) { all0 = 0; break; }
        is64 = all0;
    }
    if (t < NN) degs[t] = 1;
    __syncthreads();

    const long long* e64 = (const long long*)ei_raw;
    const int w64 = is64;

    for (int e = t; e < E; e += 256) {
        int d = w64 ? (int)e64[E + e] : e32[E + e];
        atomicAdd(&degs[d], 1);
    }
    __syncthreads();
    if (t == 0) {
        rps[0] = 0;
        for (int j = 0; j < NN; j++) rps[j + 1] = rps[j] + degs[j];
    }
    __syncthreads();
    if (t < NN) {
        dinvs[t] = rsqrtf((float)degs[t]);
        curs[t] = rps[t];
        g_rowptr[t] = rps[t];
    }
    if (t == 0) g_rowptr[NN] = rps[NN];
    __syncthreads();
    for (int e = t; e < E; e += 256) {
        int s = w64 ? (int)e64[e] : e32[e];
        int d = w64 ? (int)e64[E + e] : e32[E + e];
        float nw = dinvs[s] * dinvs[d];
        int pos = atomicAdd(&curs[d], 1);
        g_edgesP[pos] = (__float_as_uint(nw) & 0xFFFFFF00u) | (unsigned)s;
        atomicAdd(&g_Adense[d * 192 + s], nw);
    }
    if (t < NN) {
        float nw = dinvs[t] * dinvs[t];
        int pos = atomicAdd(&curs[t], 1);
        g_edgesP[pos] = (__float_as_uint(nw) & 0xFFFFFF00u) | (unsigned)t;
        atomicAdd(&g_Adense[t * 192 + t], nw);
    }
}

// ---------------- column stats of low_dim_features ----------------
__global__ void k_stats1(const float* __restrict__ low, int B) {
    const int t = threadIdx.x;
    const int c = t & 63, rg = t >> 6;
    float s = 0.f, q = 0.f;
    for (int r = blockIdx.x * 4 + rg; r < B; r += gridDim.x * 4) {
        float v = low[r * LOWD + c];
        s += v; q += v * v;
    }
    __shared__ float ss[256], qq[256];
    ss[t] = s; qq[t] = q;
    __syncthreads();
    if (rg == 0) {
        atomicAdd(&g_sum1[c], ss[c] + ss[64 + c] + ss[128 + c] + ss[192 + c]);
        atomicAdd(&g_sq1[c],  qq[c] + qq[64 + c] + qq[128 + c] + qq[192 + c]);
    }
}

// ---------------- bn1 fold + linear + relu + bn2 stats ----------------
__global__ void __launch_bounds__(128) k_lowmlp(const float* __restrict__ low,
                                                const float* __restrict__ gbn, const float* __restrict__ bbn,
                                                const float* __restrict__ Wlow, const float* __restrict__ bllow,
                                                int B) {
    __shared__ float s1[LOWD], t1[LOWD];
    __shared__ float rows[8 * LOWD];
    const int t = threadIdx.x;

    if (t < LOWD) {
        float inv = 1.f / (float)B;
        float mu  = g_sum1[t] * inv;
        float var = g_sq1[t] * inv - mu * mu;
        float sc  = gbn[t] * rsqrtf(var + BEPS);
        s1[t] = sc;
        t1[t] = bbn[t] - mu * sc;
    }
    __syncthreads();

    float w[LOWD];
    float bias = bllow[t];
    #pragma unroll
    for (int k = 0; k < LOWD; k++) {
        float v = Wlow[k * EMB + t];
        w[k] = s1[k] * v;
        bias += t1[k] * v;
    }

    const int spb = (B + gridDim.x - 1) / gridDim.x;
    float ls = 0.f, lq = 0.f;
    const int r8 = t >> 4, q16 = t & 15;

    for (int it = 0; it < spb; it += 8) {
        int base = blockIdx.x * spb + it;
        int rrow = base + r8;
        if (rrow < B)
            ((float4*)rows)[t] = ((const float4*)low)[rrow * 16 + q16];
        __syncthreads();
        #pragma unroll
        for (int s = 0; s < 8; s++) {
            int r = base + s;
            if (r < B) {
                float acc = bias;
                const float4* rp = (const float4*)(rows + s * LOWD);
                #pragma unroll
                for (int k4 = 0; k4 < 16; k4++) {
                    float4 rv = rp[k4];
                    acc += rv.x * w[k4 * 4 + 0];
                    acc += rv.y * w[k4 * 4 + 1];
                    acc += rv.z * w[k4 * 4 + 2];
                    acc += rv.w * w[k4 * 4 + 3];
                }
                acc = fmaxf(acc, 0.f);
                g_relu_low[(size_t)r * EMB + t] = acc;
                ls += acc; lq += acc * acc;
            }
        }
        __syncthreads();
    }
    atomicAdd(&g_sum2[t], ls);
    atomicAdd(&g_sq2[t], lq);
}

// ---------------- fold bn2 into fc1 ----------------
__global__ void k_fold2(const float* __restrict__ glow, const float* __restrict__ blowbn,
                        const float* __restrict__ Wfc1, const float* __restrict__ bfc1, int B) {
    __shared__ float s2[EMB], t2[EMB];
    const int t = threadIdx.x;
    if (t < EMB) {
        float inv = 1.f / (float)B;
        float mu  = g_sum2[t] * inv;
        float var = g_sq2[t] * inv - mu * mu;
        float sc  = glow[t] * rsqrtf(var + BEPS);
        s2[t] = sc;
        t2[t] = blowbn[t] - mu * sc;
    }
    __syncthreads();
    for (int i = t; i < NC * EMB; i += blockDim.x) g_Wfcf[i] = Wfc1[i];
    for (int i = t; i < EMB * EMB; i += blockDim.x) {
        int k = i >> 7;
        g_Wfcf[NC * EMB + i] = s2[k] * Wfc1[NC * EMB + i];
    }
    if (t < EMB) {
        float acc = bfc1[t];
        for (int k = 0; k < EMB; k++) acc += t2[k] * Wfc1[(NC + k) * EMB + t];
        g_bfcf[t] = acc;
    }
}

// ---------------- persistent fused GCN with mma.sync conv2 ----------------
__global__ void __launch_bounds__(512) k_gcn(const float* __restrict__ high,
                                             const float* __restrict__ W1, const float* __restrict__ b1,
                                             const float* __restrict__ W2, const float* __restrict__ b2,
                                             int EC, int B) {
    extern __shared__ char sm[];
    const int t = threadIdx.x;
    const int lane = t & 31, w = t >> 5;
    const int g = lane >> 2, tig = lane & 3;
    const int n16 = (w & 3) * 16, mg = w >> 2;

    char* AD = sm + OFF_AD;
    char* H1 = sm + OFF_H1;
    char* WT = sm + OFF_WT;
    char* ZT = sm + OFF_ZT;
    float*    xs   = (float*)(sm + OFF_XS);
    float*    y0s  = (float*)(sm + OFF_Y0);
    float*    W1s  = (float*)(sm + OFF_W1);
    float*    b1s  = (float*)(sm + OFF_B1);
    float*    b2s  = (float*)(sm + OFF_B2);
    float*    pool = (float*)(sm + OFF_POOL);
    int*      srp  = (int*)(sm + OFF_RP);
    unsigned* se   = (unsigned*)(sm + OFF_E);

    // ---- one-time images ----
    for (int i = t; i < 176 * 96; i += 512) {            // A_dense fp16 [176 x 192]
        int r = i / 96, cp = i % 96;
        float2 v = *(const float2*)(g_Adense + r * 192 + cp * 2);
        *(__half2*)(AD + swz((uint32_t)(r * 384 + cp * 4))) = __floats2half2_rn(v.x, v.y);
    }
    for (int i = t; i < 64 * 32; i += 512) {             // W2^T fp16 [64 x 64]
        int n = i >> 5, cp = i & 31;
        *(__half2*)(WT + swz((uint32_t)(n * 128 + cp * 4))) =
            __floats2half2_rn(W2[(2 * cp) * 64 + n], W2[(2 * cp + 1) * 64 + n]);
    }
    if (t < 320) {                                       // zero h1 pad rows 166..175
        int j = 166 + (t >> 5), cp = t & 31;
        *(__half2*)(H1 + swz((uint32_t)(j * 128 + cp * 4))) = __floats2half2_rn(0.f, 0.f);
    }
    for (int i = t; i < EC; i += 512) se[i] = g_edgesP[i];
    if (t < NN + 1) srp[t] = g_rowptr[t];
    if (t < 192) W1s[t] = W1[t];
    if (t < 64) { b1s[t] = b1[t]; b2s[t] = b2[t]; }
    __syncthreads();

    // ---- preload W2 B-fragments (persistent) ----
    uint32_t wfr[4][2][2];
    #pragma unroll
    for (int kk = 0; kk < 4; kk++)
        #pragma unroll
        for (int s = 0; s < 2; s++) {
            int row = n16 + s * 8 + g;
            wfr[kk][s][0] = *(const uint32_t*)(WT + swz((uint32_t)(row * 128 + (kk * 16 + tig * 2) * 2)));
            wfr[kk][s][1] = *(const uint32_t*)(WT + swz((uint32_t)(row * 128 + (kk * 16 + tig * 2 + 8) * 2)));
        }

    for (int b = blockIdx.x; b < B; b += gridDim.x) {
        // 1. zero pool; load x
        if (t < 64) pool[t] = 0.f;
        if (t < 249) ((float2*)xs)[t] = ((const float2*)(high + (size_t)b * 498))[t];
        __syncthreads();

        // 2. y0 = A x (sparse, 3 channels)
        if (t < NN * 3) {
            int j = t / 3, c = t - j * 3;
            int e0 = srp[j], e1 = srp[j + 1];
            float a = 0.f;
            for (int e = e0; e < e1; e++) {
                unsigned u = se[e];
                a += __uint_as_float(u & 0xFFFFFF00u) * xs[(u & 0xFFu) * 3 + c];
            }
            y0s[t] = a;
        }
        __syncthreads();

        // 3. h1 = relu(y0 W1 + b1) -> fp16 image
        for (int i = t; i < NN * 32; i += 512) {
            int j = i >> 5, cp = i & 31, c = cp * 2;
            float ya = y0s[3 * j], yb = y0s[3 * j + 1], yc = y0s[3 * j + 2];
            float v0 = b1s[c]     + ya * W1s[c]     + yb * W1s[64 + c]     + yc * W1s[128 + c];
            float v1 = b1s[c + 1] + ya * W1s[c + 1] + yb * W1s[64 + c + 1] + yc * W1s[128 + c + 1];
            *(__half2*)(H1 + swz((uint32_t)(j * 128 + cp * 4))) =
                __floats2half2_rn(fmaxf(v0, 0.f), fmaxf(v1, 0.f));
        }
        __syncthreads();

        // 4. GEMM1: z = h1 @ W2 -> store z^T fp16
        #pragma unroll
        for (int tt = 0; tt < 3; tt++) {
            int mt = mg + 4 * tt;
            if (mt < 11) {
                float z0[8] = {0, 0, 0, 0, 0, 0, 0, 0};
                #pragma unroll
                for (int kk = 0; kk < 4; kk++) {
                    uint32_t r0o = (uint32_t)((mt * 16 + g) * 128);
                    uint32_t r1o = (uint32_t)((mt * 16 + g + 8) * 128);
                    uint32_t c0o = (uint32_t)((kk * 16 + tig * 2) * 2);
                    uint32_t a0 = *(const uint32_t*)(H1 + swz(r0o + c0o));
                    uint32_t a1 = *(const uint32_t*)(H1 + swz(r1o + c0o));
                    uint32_t a2 = *(const uint32_t*)(H1 + swz(r0o + c0o + 16));
                    uint32_t a3 = *(const uint32_t*)(H1 + swz(r1o + c0o + 16));
                    mma8(z0,     a0, a1, a2, a3, wfr[kk][0][0], wfr[kk][0][1]);
                    mma8(z0 + 4, a0, a1, a2, a3, wfr[kk][1][0], wfr[kk][1][1]);
                }
                int m0 = mt * 16 + g, m1 = m0 + 8;
                #pragma unroll
                for (int s = 0; s < 2; s++) {
                    int c = n16 + s * 8 + tig * 2;
                    *(__half*)(ZT + swz((uint32_t)(c * 384 + m0 * 2)))       = __float2half_rn(z0[s * 4 + 0]);
                    *(__half*)(ZT + swz((uint32_t)((c + 1) * 384 + m0 * 2))) = __float2half_rn(z0[s * 4 + 1]);
                    *(__half*)(ZT + swz((uint32_t)(c * 384 + m1 * 2)))       = __float2half_rn(z0[s * 4 + 2]);
                    *(__half*)(ZT + swz((uint32_t)((c + 1) * 384 + m1 * 2))) = __float2half_rn(z0[s * 4 + 3]);
                }
            }
        }
        __syncthreads();

        // 5. GEMM2: h2 = A_dense @ z ; fused bias+relu+pool
        uint32_t bfr[11][2][2];
        #pragma unroll
        for (int kk = 0; kk < 11; kk++)
            #pragma unroll
            for (int s = 0; s < 2; s++) {
                int row = n16 + s * 8 + g;
                bfr[kk][s][0] = *(const uint32_t*)(ZT + swz((uint32_t)(row * 384 + (kk * 16 + tig * 2) * 2)));
                bfr[kk][s][1] = *(const uint32_t*)(ZT + swz((uint32_t)(row * 384 + (kk * 16 + tig * 2 + 8) * 2)));
            }

        float pacc[4] = {0, 0, 0, 0};
        #pragma unroll
        for (int tt = 0; tt < 3; tt++) {
            int mt = mg + 4 * tt;
            if (mt < 11) {
                float d0[8] = {0, 0, 0, 0, 0, 0, 0, 0};
                #pragma unroll
                for (int kk = 0; kk < 11; kk++) {
                    uint32_t r0o = (uint32_t)((mt * 16 + g) * 384);
                    uint32_t r1o = (uint32_t)((mt * 16 + g + 8) * 384);
                    uint32_t c0o = (uint32_t)((kk * 16 + tig * 2) * 2);
                    uint32_t a0 = *(const uint32_t*)(AD + swz(r0o + c0o));
                    uint32_t a1 = *(const uint32_t*)(AD + swz(r1o + c0o));
                    uint32_t a2 = *(const uint32_t*)(AD + swz(r0o + c0o + 16));
                    uint32_t a3 = *(const uint32_t*)(AD + swz(r1o + c0o + 16));
                    mma8(d0,     a0, a1, a2, a3, bfr[kk][0][0], bfr[kk][0][1]);
                    mma8(d0 + 4, a0, a1, a2, a3, bfr[kk][1][0], bfr[kk][1][1]);
                }
                int m0 = mt * 16 + g;
                bool v0 = (m0 < NN), v1 = (m0 + 8 < NN);
                #pragma unroll
                for (int s = 0; s < 2; s++) {
                    int c = n16 + s * 8 + tig * 2;
                    float bb0 = b2s[c], bb1 = b2s[c + 1];
                    if (v0) {
                        pacc[s * 2]     += fmaxf(d0[s * 4 + 0] + bb0, 0.f);
                        pacc[s * 2 + 1] += fmaxf(d0[s * 4 + 1] + bb1, 0.f);
                    }
                    if (v1) {
                        pacc[s * 2]     += fmaxf(d0[s * 4 + 2] + bb0, 0.f);
                        pacc[s * 2 + 1] += fmaxf(d0[s * 4 + 3] + bb1, 0.f);
                    }
                }
            }
        }
        // reduce over g (lane bits 2..4) then atomics by g==0 lanes
        #pragma unroll
        for (int o = 4; o <= 16; o <<= 1) {
            pacc[0] += __shfl_xor_sync(0xffffffffu, pacc[0], o);
            pacc[1] += __shfl_xor_sync(0xffffffffu, pacc[1], o);
            pacc[2] += __shfl_xor_sync(0xffffffffu, pacc[2], o);
            pacc[3] += __shfl_xor_sync(0xffffffffu, pacc[3], o);
        }
        if (g == 0) {
            atomicAdd(&pool[n16 + tig * 2],     pacc[0]);
            atomicAdd(&pool[n16 + tig * 2 + 1], pacc[1]);
            atomicAdd(&pool[n16 + 8 + tig * 2],     pacc[2]);
            atomicAdd(&pool[n16 + 8 + tig * 2 + 1], pacc[3]);
        }
        __syncthreads();
        if (t < 64) g_gfeat[(size_t)b * NC + t] = pool[t] * (1.f / (float)NN);
        __syncthreads();
    }
}

// ---------------- head ----------------
__global__ void __launch_bounds__(256) k_head(const float* __restrict__ Wcls,
                                              const float* __restrict__ bcls,
                                              float* __restrict__ out, int B) {
    const int t = threadIdx.x;
    const int c = t & 127;
    const int kh = t >> 7;

    __shared__ float comb[FCIN];
    __shared__ float partial[2 * EMB];
    __shared__ float bfcs[EMB];
    __shared__ float wcl0[EMB], wcl1[EMB];
    __shared__ float red[8];

    if (t < EMB) {
        bfcs[t] = g_bfcf[t];
        wcl0[t] = Wcls[t * 2];
        wcl1[t] = Wcls[t * 2 + 1];
    }
    float w[96];
    #pragma unroll
    for (int i = 0; i < 96; i++) w[i] = g_Wfcf[(kh * 96 + i) * EMB + c];

    const int spb = (B + gridDim.x - 1) / gridDim.x;
    __syncthreads();

    for (int it = 0; it < spb; it++) {
        int s = blockIdx.x * spb + it;
        bool valid = (s < B);
        if (valid) {
            if (t < NC) comb[t] = g_gfeat[(size_t)s * NC + t];
            int u = t - NC;
            if (u >= 0 && u < EMB) comb[NC + u] = g_relu_low[(size_t)s * EMB + u];
        }
        __syncthreads();
        if (valid) {
            const float* cb = comb + kh * 96;
            float a0 = 0.f, a1 = 0.f, a2 = 0.f, a3 = 0.f;
            #pragma unroll
            for (int i = 0; i < 96; i += 4) {
                a0 += w[i] * cb[i];
                a1 += w[i + 1] * cb[i + 1];
                a2 += w[i + 2] * cb[i + 2];
                a3 += w[i + 3] * cb[i + 3];
            }
            partial[kh * EMB + c] = (a0 + a1) + (a2 + a3);
        }
        __syncthreads();
        if (valid && kh == 0) {
            float h = fmaxf(partial[c] + partial[EMB + c] + bfcs[c], 0.f);
            float p0 = h * wcl0[c];
            float p1 = h * wcl1[c];
            #pragma unroll
            for (int o = 16; o > 0; o >>= 1) {
                p0 += __shfl_down_sync(0xffffffffu, p0, o);
                p1 += __shfl_down_sync(0xffffffffu, p1, o);
            }
            if ((c & 31) == 0) { red[c >> 5] = p0; red[4 + (c >> 5)] = p1; }
        }
        __syncthreads();
        if (valid && t == 0) {
            float l0 = red[0] + red[1] + red[2] + red[3] + bcls[0];
            float l1 = red[4] + red[5] + red[6] + red[7] + bcls[1];
            float m = fmaxf(l0, l1);
            float lse = m + logf(expf(l0 - m) + expf(l1 - m));
            out[(size_t)s * 2 + 0] = l0 - lse;
            out[(size_t)s * 2 + 1] = l1 - lse;
        }
        __syncthreads();
    }
}

// ---------------- launch ----------------
extern "C" void kernel_launch(void* const* d_in, const int* in_sizes, int n_in,
                              void* d_out, int out_size) {
    const float* high  = (const float*)d_in[0];
    const float* low   = (const float*)d_in[1];
    const void*  ei    = d_in[2];
    const float* g_bn  = (const float*)d_in[3];
    const float* b_bn  = (const float*)d_in[4];
    const float* W_low = (const float*)d_in[5];
    const float* bl_lw = (const float*)d_in[6];
    const float* g_lo  = (const float*)d_in[7];
    const float* b_lo  = (const float*)d_in[8];
    const float* W1    = (const float*)d_in[9];
    const float* b1    = (const float*)d_in[10];
    const float* W2    = (const float*)d_in[11];
    const float* b2    = (const float*)d_in[12];
    const float* Wfc1  = (const float*)d_in[13];
    const float* bfc1  = (const float*)d_in[14];
    const float* Wcls  = (const float*)d_in[15];
    const float* bcls  = (const float*)d_in[16];

    int B = in_sizes[0] / (NN * 3);
    int E = in_sizes[2] / 2;
    int EC = E + NN;
    if (EC > 4352) EC = 4352;
    float* out = (float*)d_out;

    k_graph<<<1, 256>>>(ei, E);
    k_stats1<<<64, 256>>>(low, B);
    k_lowmlp<<<128, 128>>>(low, g_bn, b_bn, W_low, bl_lw, B);

    cudaFuncSetAttribute(k_gcn, cudaFuncAttributeMaxDynamicSharedMemorySize, GCN_SMEM);
    int grid = 148;
    if (grid > B) grid = B;
    k_gcn<<<grid, 512, GCN_SMEM>>>(high, W1, b1, W2, b2, EC, B);

    k_fold2<<<1, 256>>>(g_lo, b_lo, Wfc1, bfc1, B);
    k_head<<<128, 256>>>(Wcls, bcls, out, B);
}

// round 8
// speedup vs baseline: 2.8935x; 1.0904x over previous
#include <cuda_runtime.h>
#include <cuda_fp16.h>
#include <math.h>
#include <stdint.h>

#define NN   166
#define NC   64
#define EMB  128
#define LOWD 64
#define FCIN 192
#define BEPS 1e-5f
#define MAXB 8192
#define MAXE 131072

// ---- k_gcn smem layout (bytes; every image offset 1024-aligned) ----
#define OFF_AD   0        // A_dense fp16 [176 x 192] swz      67584
#define OFF_H1   67584    // h1 fp16 [176 x 64] swz            22528
#define OFF_WT   90112    // W2^T fp16 [64 x 64] swz            8192
#define OFF_ZT   98304    // z^T fp16 [64 x 192] swz           24576
#define OFF_E    122880   // packed edges (cap 4352)           17408
#define OFF_XS   140288   // x fp32 (498, padded)               2048
#define OFF_Y0   142336   // y0 fp32 (498, padded)              2048
#define OFF_RP   144384   // rowptr (168)                        672
#define OFF_B1   145056   // b1 fp32 (64)
#define OFF_B2   145312   // b2 fp32 (64)
#define OFF_W1   145568   // W1 fp32 (192)
#define OFF_POOL 146336   // pool fp32 (64)
#define GCN_SMEM 146592

// ---------------- device scratch ----------------
__device__ unsigned g_edgesP[MAXE];
__device__ int   g_rowptr[NN + 1];
__device__ float g_Adense[256 * 192];
__device__ float g_sum1[LOWD], g_sq1[LOWD];
__device__ float g_sum2[EMB],  g_sq2[EMB];
__device__ float g_Wfcf[FCIN * EMB],  g_bfcf[EMB];
__device__ float g_relu_low[MAXB * EMB];
__device__ float g_gfeat[MAXB * NC];

// ---------------- helpers ----------------
__device__ __forceinline__ uint32_t swz(uint32_t o) { return o ^ ((o >> 3) & 0x70); }

__device__ __forceinline__ uint32_t smem_u32(const void* p) {
    uint32_t a;
    asm("{ .reg .u64 t; cvta.to.shared.u64 t, %1; cvt.u32.u64 %0, t; }" : "=r"(a) : "l"(p));
    return a;
}

__device__ __forceinline__ void mma8(float* d, uint32_t a0, uint32_t a1, uint32_t a2, uint32_t a3,
                                     uint32_t b0, uint32_t b1) {
    asm volatile(
        "mma.sync.aligned.m16n8k16.row.col.f32.f16.f16.f32 "
        "{%0,%1,%2,%3}, {%4,%5,%6,%7}, {%8,%9}, {%0,%1,%2,%3};"
        : "+f"(d[0]), "+f"(d[1]), "+f"(d[2]), "+f"(d[3])
        : "r"(a0), "r"(a1), "r"(a2), "r"(a3), "r"(b0), "r"(b1));
}

__device__ __forceinline__ void ldsm4(uint32_t& a0, uint32_t& a1, uint32_t& a2, uint32_t& a3,
                                      uint32_t addr) {
    asm volatile("ldmatrix.sync.aligned.m8n8.x4.shared.b16 {%0,%1,%2,%3}, [%4];"
                 : "=r"(a0), "=r"(a1), "=r"(a2), "=r"(a3) : "r"(addr));
}

__device__ __forceinline__ void stsm4t(uint32_t addr, uint32_t x0, uint32_t x1,
                                       uint32_t x2, uint32_t x3) {
    asm volatile("stmatrix.sync.aligned.m8n8.x4.trans.shared.b16 [%0], {%1,%2,%3,%4};"
                 :: "r"(addr), "r"(x0), "r"(x1), "r"(x2), "r"(x3) : "memory");
}

__device__ __forceinline__ uint32_t packh2(float a, float b) {
    __half2 h = __floats2half2_rn(a, b);
    return *(uint32_t*)&h;
}

// ---------------- CSR + dense A build; zero stats ----------------
__global__ void k_graph(const void* __restrict__ ei_raw, int E) {
    __shared__ int   degs[NN];
    __shared__ float dinvs[NN];
    __shared__ int   curs[NN];
    __shared__ int   rps[NN + 1];
    __shared__ int   is64;

    const int t = threadIdx.x;
    const int* e32 = (const int*)ei_raw;

    for (int i = t; i < 256 * 192; i += 256) g_Adense[i] = 0.f;
    if (t < LOWD) { g_sum1[t] = 0.f; g_sq1[t] = 0.f; }
    if (t < EMB)  { g_sum2[t] = 0.f; g_sq2[t] = 0.f; }

    if (t == 0) {
        int all0 = 1;
        int lim = 2 * E; if (lim > 512) lim = 512;
        for (int i = 1; i < lim; i += 2) if (e32[i] != 0) { all0 = 0; break; }
        is64 = all0;
    }
    if (t < NN) degs[t] = 1;
    __syncthreads();

    const long long* e64 = (const long long*)ei_raw;
    const int w64 = is64;

    for (int e = t; e < E; e += 256) {
        int d = w64 ? (int)e64[E + e] : e32[E + e];
        atomicAdd(&degs[d], 1);
    }
    __syncthreads();
    if (t == 0) {
        rps[0] = 0;
        for (int j = 0; j < NN; j++) rps[j + 1] = rps[j] + degs[j];
    }
    __syncthreads();
    if (t < NN) {
        dinvs[t] = rsqrtf((float)degs[t]);
        curs[t] = rps[t];
        g_rowptr[t] = rps[t];
    }
    if (t == 0) g_rowptr[NN] = rps[NN];
    __syncthreads();
    for (int e = t; e < E; e += 256) {
        int s = w64 ? (int)e64[e] : e32[e];
        int d = w64 ? (int)e64[E + e] : e32[E + e];
        float nw = dinvs[s] * dinvs[d];
        int pos = atomicAdd(&curs[d], 1);
        g_edgesP[pos] = (__float_as_uint(nw) & 0xFFFFFF00u) | (unsigned)s;
        atomicAdd(&g_Adense[d * 192 + s], nw);
    }
    if (t < NN) {
        float nw = dinvs[t] * dinvs[t];
        int pos = atomicAdd(&curs[t], 1);
        g_edgesP[pos] = (__float_as_uint(nw) & 0xFFFFFF00u) | (unsigned)t;
        atomicAdd(&g_Adense[t * 192 + t], nw);
    }
}

// ---------------- column stats of low_dim_features ----------------
__global__ void k_stats1(const float* __restrict__ low, int B) {
    const int t = threadIdx.x;
    const int c = t & 63, rg = t >> 6;
    float s = 0.f, q = 0.f;
    for (int r = blockIdx.x * 4 + rg; r < B; r += gridDim.x * 4) {
        float v = low[r * LOWD + c];
        s += v; q += v * v;
    }
    __shared__ float ss[256], qq[256];
    ss[t] = s; qq[t] = q;
    __syncthreads();
    if (rg == 0) {
        atomicAdd(&g_sum1[c], ss[c] + ss[64 + c] + ss[128 + c] + ss[192 + c]);
        atomicAdd(&g_sq1[c],  qq[c] + qq[64 + c] + qq[128 + c] + qq[192 + c]);
    }
}

// ---------------- bn1 fold + linear + relu + bn2 stats ----------------
__global__ void __launch_bounds__(128) k_lowmlp(const float* __restrict__ low,
                                                const float* __restrict__ gbn, const float* __restrict__ bbn,
                                                const float* __restrict__ Wlow, const float* __restrict__ bllow,
                                                int B) {
    __shared__ float s1[LOWD], t1[LOWD];
    __shared__ float rows[8 * LOWD];
    const int t = threadIdx.x;

    if (t < LOWD) {
        float inv = 1.f / (float)B;
        float mu  = g_sum1[t] * inv;
        float var = g_sq1[t] * inv - mu * mu;
        float sc  = gbn[t] * rsqrtf(var + BEPS);
        s1[t] = sc;
        t1[t] = bbn[t] - mu * sc;
    }
    __syncthreads();

    float w[LOWD];
    float bias = bllow[t];
    #pragma unroll
    for (int k = 0; k < LOWD; k++) {
        float v = Wlow[k * EMB + t];
        w[k] = s1[k] * v;
        bias += t1[k] * v;
    }

    const int spb = (B + gridDim.x - 1) / gridDim.x;
    float ls = 0.f, lq = 0.f;
    const int r8 = t >> 4, q16 = t & 15;

    for (int it = 0; it < spb; it += 8) {
        int base = blockIdx.x * spb + it;
        int rrow = base + r8;
        if (rrow < B)
            ((float4*)rows)[t] = ((const float4*)low)[rrow * 16 + q16];
        __syncthreads();
        #pragma unroll
        for (int s = 0; s < 8; s++) {
            int r = base + s;
            if (r < B) {
                float acc = bias;
                const float4* rp = (const float4*)(rows + s * LOWD);
                #pragma unroll
                for (int k4 = 0; k4 < 16; k4++) {
                    float4 rv = rp[k4];
                    acc += rv.x * w[k4 * 4 + 0];
                    acc += rv.y * w[k4 * 4 + 1];
                    acc += rv.z * w[k4 * 4 + 2];
                    acc += rv.w * w[k4 * 4 + 3];
                }
                acc = fmaxf(acc, 0.f);
                g_relu_low[(size_t)r * EMB + t] = acc;
                ls += acc; lq += acc * acc;
            }
        }
        __syncthreads();
    }
    atomicAdd(&g_sum2[t], ls);
    atomicAdd(&g_sq2[t], lq);
}

// ---------------- fold bn2 into fc1 ----------------
__global__ void k_fold2(const float* __restrict__ glow, const float* __restrict__ blowbn,
                        const float* __restrict__ Wfc1, const float* __restrict__ bfc1, int B) {
    __shared__ float s2[EMB], t2[EMB];
    const int t = threadIdx.x;
    if (t < EMB) {
        float inv = 1.f / (float)B;
        float mu  = g_sum2[t] * inv;
        float var = g_sq2[t] * inv - mu * mu;
        float sc  = glow[t] * rsqrtf(var + BEPS);
        s2[t] = sc;
        t2[t] = blowbn[t] - mu * sc;
    }
    __syncthreads();
    for (int i = t; i < NC * EMB; i += blockDim.x) g_Wfcf[i] = Wfc1[i];
    for (int i = t; i < EMB * EMB; i += blockDim.x) {
        int k = i >> 7;
        g_Wfcf[NC * EMB + i] = s2[k] * Wfc1[NC * EMB + i];
    }
    if (t < EMB) {
        float acc = bfc1[t];
        for (int k = 0; k < EMB; k++) acc += t2[k] * Wfc1[(NC + k) * EMB + t];
        g_bfcf[t] = acc;
    }
}

// ---------------- persistent fused GCN: mma.sync + ldmatrix/stmatrix ----------------
__global__ void __launch_bounds__(512) k_gcn(const float* __restrict__ high,
                                             const float* __restrict__ W1, const float* __restrict__ b1,
                                             const float* __restrict__ W2, const float* __restrict__ b2,
                                             int EC, int B) {
    extern __shared__ char sm[];
    const int t = threadIdx.x;
    const int lane = t & 31, w = t >> 5;
    const int g = lane >> 2, tig = lane & 3;
    const int n16 = (w & 3) * 16, mg = w >> 2;

    char* AD = sm + OFF_AD;
    char* H1 = sm + OFF_H1;
    char* WT = sm + OFF_WT;
    float*    xs   = (float*)(sm + OFF_XS);
    float*    y0s  = (float*)(sm + OFF_Y0);
    float*    W1s  = (float*)(sm + OFF_W1);
    float*    b1s  = (float*)(sm + OFF_B1);
    float*    b2s  = (float*)(sm + OFF_B2);
    float*    pool = (float*)(sm + OFF_POOL);
    int*      srp  = (int*)(sm + OFF_RP);
    unsigned* se   = (unsigned*)(sm + OFF_E);

    const uint32_t sb = smem_u32(sm);

    // per-lane ldmatrix/stmatrix address bases
    const int lr = lane & 15, lc8 = (lane >> 4) * 8;
    const uint32_t aH1 = (uint32_t)(lr * 128 + lc8 * 2);   // + mt*2048 + kk*32, swz
    const uint32_t aAD = (uint32_t)(lr * 384 + lc8 * 2);   // + mt*6144 + kk*32, swz
    const int zrow = n16 + (lane & 7) + ((lane >> 4) << 3);
    const uint32_t aZT = (uint32_t)(zrow * 384 + ((lane & 8) ? 16 : 0));  // + kk*32 (ld) / + mt*32 (st)

    // ---- one-time images ----
    for (int i = t; i < 176 * 96; i += 512) {            // A_dense fp16 [176 x 192]
        int r = i / 96, cp = i % 96;
        float2 v = *(const float2*)(g_Adense + r * 192 + cp * 2);
        *(__half2*)(AD + swz((uint32_t)(r * 384 + cp * 4))) = __floats2half2_rn(v.x, v.y);
    }
    for (int i = t; i < 64 * 32; i += 512) {             // W2^T fp16 [64 x 64]
        int n = i >> 5, cp = i & 31;
        *(__half2*)(WT + swz((uint32_t)(n * 128 + cp * 4))) =
            __floats2half2_rn(W2[(2 * cp) * 64 + n], W2[(2 * cp + 1) * 64 + n]);
    }
    if (t < 320) {                                       // zero h1 pad rows 166..175
        int j = 166 + (t >> 5), cp = t & 31;
        *(__half2*)(H1 + swz((uint32_t)(j * 128 + cp * 4))) = __floats2half2_rn(0.f, 0.f);
    }
    for (int i = t; i < EC; i += 512) se[i] = g_edgesP[i];
    if (t < NN + 1) srp[t] = g_rowptr[t];
    if (t < 192) W1s[t] = W1[t];
    if (t < 64) { b1s[t] = b1[t]; b2s[t] = b2[t]; }
    __syncthreads();

    // ---- preload W2 B-fragments (persistent across samples) ----
    uint32_t wfr[4][2][2];
    #pragma unroll
    for (int kk = 0; kk < 4; kk++)
        #pragma unroll
        for (int s = 0; s < 2; s++) {
            int row = n16 + s * 8 + g;
            wfr[kk][s][0] = *(const uint32_t*)(WT + swz((uint32_t)(row * 128 + (kk * 16 + tig * 2) * 2)));
            wfr[kk][s][1] = *(const uint32_t*)(WT + swz((uint32_t)(row * 128 + (kk * 16 + tig * 2 + 8) * 2)));
        }

    for (int b = blockIdx.x; b < B; b += gridDim.x) {
        // 1. zero pool; load x
        if (t < 64) pool[t] = 0.f;
        if (t < 249) ((float2*)xs)[t] = ((const float2*)(high + (size_t)b * 498))[t];
        __syncthreads();

        // 2. y0 = A x (sparse, 3 channels)
        if (t < NN * 3) {
            int j = t / 3, c = t - j * 3;
            int e0 = srp[j], e1 = srp[j + 1];
            float a = 0.f;
            for (int e = e0; e < e1; e++) {
                unsigned u = se[e];
                a += __uint_as_float(u & 0xFFFFFF00u) * xs[(u & 0xFFu) * 3 + c];
            }
            y0s[t] = a;
        }
        __syncthreads();

        // 3. h1 = relu(y0 W1 + b1) -> fp16 image
        for (int i = t; i < NN * 32; i += 512) {
            int j = i >> 5, cp = i & 31, c = cp * 2;
            float ya = y0s[3 * j], yb = y0s[3 * j + 1], yc = y0s[3 * j + 2];
            float v0 = b1s[c]     + ya * W1s[c]     + yb * W1s[64 + c]     + yc * W1s[128 + c];
            float v1 = b1s[c + 1] + ya * W1s[c + 1] + yb * W1s[64 + c + 1] + yc * W1s[128 + c + 1];
            *(__half2*)(H1 + swz((uint32_t)(j * 128 + cp * 4))) =
                __floats2half2_rn(fmaxf(v0, 0.f), fmaxf(v1, 0.f));
        }
        __syncthreads();

        // 4. GEMM1: z = h1 @ W2 -> stmatrix.trans into z^T
        #pragma unroll
        for (int tt = 0; tt < 3; tt++) {
            int mt = mg + 4 * tt;
            if (mt < 11) {
                float z0[8] = {0, 0, 0, 0, 0, 0, 0, 0};
                #pragma unroll
                for (int kk = 0; kk < 4; kk++) {
                    uint32_t a0, a1, a2, a3;
                    ldsm4(a0, a1, a2, a3,
                          sb + OFF_H1 + swz((uint32_t)(mt * 2048 + kk * 32) + aH1));
                    mma8(z0,     a0, a1, a2, a3, wfr[kk][0][0], wfr[kk][0][1]);
                    mma8(z0 + 4, a0, a1, a2, a3, wfr[kk][1][0], wfr[kk][1][1]);
                }
                stsm4t(sb + OFF_ZT + swz(aZT + (uint32_t)(mt * 32)),
                       packh2(z0[0], z0[1]), packh2(z0[2], z0[3]),
                       packh2(z0[4], z0[5]), packh2(z0[6], z0[7]));
            }
        }
        __syncthreads();

        // 5. GEMM2: h2 = A_dense @ z ; fused bias+relu+pool
        uint32_t bfr[11][4];
        #pragma unroll
        for (int kk = 0; kk < 11; kk++)
            ldsm4(bfr[kk][0], bfr[kk][1], bfr[kk][2], bfr[kk][3],
                  sb + OFF_ZT + swz(aZT + (uint32_t)(kk * 32)));

        float pacc[4] = {0, 0, 0, 0};
        #pragma unroll
        for (int tt = 0; tt < 3; tt++) {
            int mt = mg + 4 * tt;
            if (mt < 11) {
                float d0[8] = {0, 0, 0, 0, 0, 0, 0, 0};
                #pragma unroll
                for (int kk = 0; kk < 11; kk++) {
                    uint32_t a0, a1, a2, a3;
                    ldsm4(a0, a1, a2, a3,
                          sb + OFF_AD + swz((uint32_t)(mt * 6144 + kk * 32) + aAD));
                    mma8(d0,     a0, a1, a2, a3, bfr[kk][0], bfr[kk][1]);
                    mma8(d0 + 4, a0, a1, a2, a3, bfr[kk][2], bfr[kk][3]);
                }
                int m0 = mt * 16 + g;
                bool v0 = (m0 < NN), v1 = (m0 + 8 < NN);
                #pragma unroll
                for (int s = 0; s < 2; s++) {
                    int c = n16 + s * 8 + tig * 2;
                    float bb0 = b2s[c], bb1 = b2s[c + 1];
                    if (v0) {
                        pacc[s * 2]     += fmaxf(d0[s * 4 + 0] + bb0, 0.f);
                        pacc[s * 2 + 1] += fmaxf(d0[s * 4 + 1] + bb1, 0.f);
                    }
                    if (v1) {
                        pacc[s * 2]     += fmaxf(d0[s * 4 + 2] + bb0, 0.f);
                        pacc[s * 2 + 1] += fmaxf(d0[s * 4 + 3] + bb1, 0.f);
                    }
                }
            }
        }
        // reduce over g (lane bits 2..4), then one atomic per surviving lane
        #pragma unroll
        for (int o = 4; o <= 16; o <<= 1) {
            pacc[0] += __shfl_xor_sync(0xffffffffu, pacc[0], o);
            pacc[1] += __shfl_xor_sync(0xffffffffu, pacc[1], o);
            pacc[2] += __shfl_xor_sync(0xffffffffu, pacc[2], o);
            pacc[3] += __shfl_xor_sync(0xffffffffu, pacc[3], o);
        }
        if (g == 0) {
            atomicAdd(&pool[n16 + tig * 2],     pacc[0]);
            atomicAdd(&pool[n16 + tig * 2 + 1], pacc[1]);
            atomicAdd(&pool[n16 + 8 + tig * 2],     pacc[2]);
            atomicAdd(&pool[n16 + 8 + tig * 2 + 1], pacc[3]);
        }
        __syncthreads();
        if (t < 64) g_gfeat[(size_t)b * NC + t] = pool[t] * (1.f / (float)NN);
        __syncthreads();
    }
}

// ---------------- head ----------------
__global__ void __launch_bounds__(256) k_head(const float* __restrict__ Wcls,
                                              const float* __restrict__ bcls,
                                              float* __restrict__ out, int B) {
    const int t = threadIdx.x;
    const int c = t & 127;
    const int kh = t >> 7;

    __shared__ float comb[FCIN];
    __shared__ float partial[2 * EMB];
    __shared__ float bfcs[EMB];
    __shared__ float wcl0[EMB], wcl1[EMB];
    __shared__ float red[8];

    if (t < EMB) {
        bfcs[t] = g_bfcf[t];
        wcl0[t] = Wcls[t * 2];
        wcl1[t] = Wcls[t * 2 + 1];
    }
    float w[96];
    #pragma unroll
    for (int i = 0; i < 96; i++) w[i] = g_Wfcf[(kh * 96 + i) * EMB + c];

    const int spb = (B + gridDim.x - 1) / gridDim.x;
    __syncthreads();

    for (int it = 0; it < spb; it++) {
        int s = blockIdx.x * spb + it;
        bool valid = (s < B);
        if (valid) {
            if (t < NC) comb[t] = g_gfeat[(size_t)s * NC + t];
            int u = t - NC;
            if (u >= 0 && u < EMB) comb[NC + u] = g_relu_low[(size_t)s * EMB + u];
        }
        __syncthreads();
        if (valid) {
            const float* cb = comb + kh * 96;
            float a0 = 0.f, a1 = 0.f, a2 = 0.f, a3 = 0.f;
            #pragma unroll
            for (int i = 0; i < 96; i += 4) {
                a0 += w[i] * cb[i];
                a1 += w[i + 1] * cb[i + 1];
                a2 += w[i + 2] * cb[i + 2];
                a3 += w[i + 3] * cb[i + 3];
            }
            partial[kh * EMB + c] = (a0 + a1) + (a2 + a3);
        }
        __syncthreads();
        if (valid && kh == 0) {
            float h = fmaxf(partial[c] + partial[EMB + c] + bfcs[c], 0.f);
            float p0 = h * wcl0[c];
            float p1 = h * wcl1[c];
            #pragma unroll
            for (int o = 16; o > 0; o >>= 1) {
                p0 += __shfl_down_sync(0xffffffffu, p0, o);
                p1 += __shfl_down_sync(0xffffffffu, p1, o);
            }
            if ((c & 31) == 0) { red[c >> 5] = p0; red[4 + (c >> 5)] = p1; }
        }
        __syncthreads();
        if (valid && t == 0) {
            float l0 = red[0] + red[1] + red[2] + red[3] + bcls[0];
            float l1 = red[4] + red[5] + red[6] + red[7] + bcls[1];
            float m = fmaxf(l0, l1);
            float lse = m + logf(expf(l0 - m) + expf(l1 - m));
            out[(size_t)s * 2 + 0] = l0 - lse;
            out[(size_t)s * 2 + 1] = l1 - lse;
        }
        __syncthreads();
    }
}

// ---------------- launch ----------------
extern "C" void kernel_launch(void* const* d_in, const int* in_sizes, int n_in,
                              void* d_out, int out_size) {
    const float* high  = (const float*)d_in[0];
    const float* low   = (const float*)d_in[1];
    const void*  ei    = d_in[2];
    const float* g_bn  = (const float*)d_in[3];
    const float* b_bn  = (const float*)d_in[4];
    const float* W_low = (const float*)d_in[5];
    const float* bl_lw = (const float*)d_in[6];
    const float* g_lo  = (const float*)d_in[7];
    const float* b_lo  = (const float*)d_in[8];
    const float* W1    = (const float*)d_in[9];
    const float* b1    = (const float*)d_in[10];
    const float* W2    = (const float*)d_in[11];
    const float* b2    = (const float*)d_in[12];
    const float* Wfc1  = (const float*)d_in[13];
    const float* bfc1  = (const float*)d_in[14];
    const float* Wcls  = (const float*)d_in[15];
    const float* bcls  = (const float*)d_in[16];

    int B = in_sizes[0] / (NN * 3);
    int E = in_sizes[2] / 2;
    int EC = E + NN;
    if (EC > 4352) EC = 4352;
    float* out = (float*)d_out;

    k_graph<<<1, 256>>>(ei, E);
    k_stats1<<<64, 256>>>(low, B);
    k_lowmlp<<<128, 128>>>(low, g_bn, b_bn, W_low, bl_lw, B);

    cudaFuncSetAttribute(k_gcn, cudaFuncAttributeMaxDynamicSharedMemorySize, GCN_SMEM);
    int grid = 148;
    if (grid > B) grid = B;
    k_gcn<<<grid, 512, GCN_SMEM>>>(high, W1, b1, W2, b2, EC, B);

    k_fold2<<<1, 256>>>(g_lo, b_lo, Wfc1, bfc1, B);
    k_head<<<128, 256>>>(Wcls, bcls, out, B);
}